// round 8
// baseline (speedup 1.0000x reference)
#include <cuda_runtime.h>
#include <cuda_bf16.h>
#include <math.h>

// Problem constants
#define Bc 2
#define Nc 2048
#define Dc 1024
#define Hc 16
#define HDc 64
#define BH (Bc * Hc)          // 32
#define MROWS (Bc * Nc)       // 4096
#define OUT_ELEMS ((size_t)Bc * Nc * Dc)              // 4,194,304

// Scratch (static device memory — no runtime allocation)
__device__ float g_Q[MROWS * Dc];
__device__ float g_K[MROWS * Dc];
__device__ float g_V[MROWS * Dc];
__device__ float g_Vt[MROWS * Dc];

#define SM_PAD 132   // 128 + 4 pad, keeps float4 alignment (132*4 % 16 == 0)

// ---------------------------------------------------------------------------
// Projection GEMM: C[M,N] = X[M,K] @ W[N,K]^T + bias   (row-major)
// 128x128 tile, BK=16, 256 threads, 8x8 per thread.
// grid = (N/128, M/128)
// ---------------------------------------------------------------------------
__global__ void gemm_nt_bias(const float* __restrict__ X, const float* __restrict__ W,
                             const float* __restrict__ bias, float* __restrict__ C,
                             int K, int N) {
    __shared__ float As[16][SM_PAD];
    __shared__ float Bs[16][SM_PAD];
    const int tid = threadIdx.x;                 // 256
    const int row0 = blockIdx.y * 128;
    const int col0 = blockIdx.x * 128;
    const int tr = tid >> 4, tc = tid & 15;

    float acc[8][8] = {};

    for (int kt = 0; kt < K; kt += 16) {
        #pragma unroll
        for (int i = 0; i < 2; i++) {
            int lin = tid + i * 256;
            int r = lin >> 2;
            int kq = (lin & 3) * 4;
            float4 xa = *(const float4*)&X[(size_t)(row0 + r) * K + kt + kq];
            float4 wb = *(const float4*)&W[(size_t)(col0 + r) * K + kt + kq];
            As[kq + 0][r] = xa.x; As[kq + 1][r] = xa.y;
            As[kq + 2][r] = xa.z; As[kq + 3][r] = xa.w;
            Bs[kq + 0][r] = wb.x; Bs[kq + 1][r] = wb.y;
            Bs[kq + 2][r] = wb.z; Bs[kq + 3][r] = wb.w;
        }
        __syncthreads();
        #pragma unroll
        for (int kk = 0; kk < 16; kk++) {
            float a[8], b[8];
            *(float4*)&a[0] = *(const float4*)&As[kk][tr * 8];
            *(float4*)&a[4] = *(const float4*)&As[kk][tr * 8 + 4];
            *(float4*)&b[0] = *(const float4*)&Bs[kk][tc * 8];
            *(float4*)&b[4] = *(const float4*)&Bs[kk][tc * 8 + 4];
            #pragma unroll
            for (int i = 0; i < 8; i++)
                #pragma unroll
                for (int j = 0; j < 8; j++)
                    acc[i][j] = fmaf(a[i], b[j], acc[i][j]);
        }
        __syncthreads();
    }

    #pragma unroll
    for (int i = 0; i < 8; i++) {
        const int r = row0 + tr * 8 + i;
        float* dst = &C[(size_t)r * N + col0 + tc * 8];
        #pragma unroll
        for (int j = 0; j < 8; j++)
            dst[j] = acc[i][j] + bias[col0 + tc * 8 + j];
    }
}

// ---------------------------------------------------------------------------
// A = scale * Q_h @ K_h^T per (b,h).  128x128 tile, K=64 (BK=16, 4 iters).
// grid = (16, 16, 32)
// ---------------------------------------------------------------------------
__global__ void qk128(const float* __restrict__ Q, const float* __restrict__ K,
                      float* __restrict__ A) {
    __shared__ float Qs[16][SM_PAD];
    __shared__ float Ks[16][SM_PAD];
    const int bh = blockIdx.z;
    const int b = bh >> 4, h = bh & 15;
    const int i0 = blockIdx.y * 128;
    const int j0 = blockIdx.x * 128;
    const int tid = threadIdx.x;
    const int tr = tid >> 4, tc = tid & 15;

    const float* Qb = Q + (size_t)b * Nc * Dc + h * HDc;
    const float* Kb = K + (size_t)b * Nc * Dc + h * HDc;

    float acc[8][8] = {};

    for (int kt = 0; kt < HDc; kt += 16) {
        #pragma unroll
        for (int i = 0; i < 2; i++) {
            int lin = tid + i * 256;
            int r = lin >> 2;
            int kq = (lin & 3) * 4;
            float4 qv = *(const float4*)&Qb[(size_t)(i0 + r) * Dc + kt + kq];
            float4 kv = *(const float4*)&Kb[(size_t)(j0 + r) * Dc + kt + kq];
            Qs[kq + 0][r] = qv.x; Qs[kq + 1][r] = qv.y;
            Qs[kq + 2][r] = qv.z; Qs[kq + 3][r] = qv.w;
            Ks[kq + 0][r] = kv.x; Ks[kq + 1][r] = kv.y;
            Ks[kq + 2][r] = kv.z; Ks[kq + 3][r] = kv.w;
        }
        __syncthreads();
        #pragma unroll
        for (int kk = 0; kk < 16; kk++) {
            float a[8], bv[8];
            *(float4*)&a[0]  = *(const float4*)&Qs[kk][tr * 8];
            *(float4*)&a[4]  = *(const float4*)&Qs[kk][tr * 8 + 4];
            *(float4*)&bv[0] = *(const float4*)&Ks[kk][tc * 8];
            *(float4*)&bv[4] = *(const float4*)&Ks[kk][tc * 8 + 4];
            #pragma unroll
            for (int i = 0; i < 8; i++)
                #pragma unroll
                for (int j = 0; j < 8; j++)
                    acc[i][j] = fmaf(a[i], bv[j], acc[i][j]);
        }
        __syncthreads();
    }

    const float scale = 0.125f;
    float* Ab = A + (size_t)bh * Nc * Nc;
    #pragma unroll
    for (int i = 0; i < 8; i++) {
        const int r = i0 + tr * 8 + i;
        float4 v0, v1;
        v0.x = acc[i][0] * scale; v0.y = acc[i][1] * scale;
        v0.z = acc[i][2] * scale; v0.w = acc[i][3] * scale;
        v1.x = acc[i][4] * scale; v1.y = acc[i][5] * scale;
        v1.z = acc[i][6] * scale; v1.w = acc[i][7] * scale;
        *(float4*)&Ab[(size_t)r * Nc + j0 + tc * 8]     = v0;
        *(float4*)&Ab[(size_t)r * Nc + j0 + tc * 8 + 4] = v1;
    }
}

// ---------------------------------------------------------------------------
// Row softmax in place, register-resident (8 floats/thread). 256 threads/row.
// ---------------------------------------------------------------------------
__global__ void softmax_kernel(float* __restrict__ A) {
    __shared__ float red[256];
    float4* p = (float4*)(A + (size_t)blockIdx.x * Nc);  // 512 float4
    const int t = threadIdx.x;

    float4 v0 = p[t];
    float4 v1 = p[t + 256];

    float m = fmaxf(fmaxf(fmaxf(v0.x, v0.y), fmaxf(v0.z, v0.w)),
                    fmaxf(fmaxf(v1.x, v1.y), fmaxf(v1.z, v1.w)));
    red[t] = m;
    __syncthreads();
    #pragma unroll
    for (int s = 128; s > 0; s >>= 1) {
        if (t < s) red[t] = fmaxf(red[t], red[t + s]);
        __syncthreads();
    }
    const float mx = red[0];
    __syncthreads();

    v0.x = __expf(v0.x - mx); v0.y = __expf(v0.y - mx);
    v0.z = __expf(v0.z - mx); v0.w = __expf(v0.w - mx);
    v1.x = __expf(v1.x - mx); v1.y = __expf(v1.y - mx);
    v1.z = __expf(v1.z - mx); v1.w = __expf(v1.w - mx);

    float sum = (v0.x + v0.y + v0.z + v0.w) + (v1.x + v1.y + v1.z + v1.w);
    red[t] = sum;
    __syncthreads();
    #pragma unroll
    for (int s = 128; s > 0; s >>= 1) {
        if (t < s) red[t] += red[t + s];
        __syncthreads();
    }
    const float inv = 1.f / red[0];

    v0.x *= inv; v0.y *= inv; v0.z *= inv; v0.w *= inv;
    v1.x *= inv; v1.y *= inv; v1.z *= inv; v1.w *= inv;
    p[t] = v0;
    p[t + 256] = v1;
}

// ---------------------------------------------------------------------------
// Vt = A @ V_h per (b,h), head-interleaved output. 128x64 tile, BK=16,
// 128 threads, 8x8 per thread. grid = (16, 32)
// ---------------------------------------------------------------------------
__global__ void av128(const float* __restrict__ A, const float* __restrict__ V,
                      float* __restrict__ Vt) {
    __shared__ float As[16][SM_PAD];
    __shared__ float Vs[16][64];
    const int bh = blockIdx.y;
    const int b = bh >> 4, h = bh & 15;
    const int i0 = blockIdx.x * 128;
    const int tid = threadIdx.x;                 // 128
    const int tr = tid >> 3, tc = tid & 7;       // 16 x 8

    const float* Ab = A + (size_t)bh * Nc * Nc;
    const float* Vb = V + (size_t)b * Nc * Dc + h * HDc;

    float acc[8][8] = {};

    for (int kt = 0; kt < Nc; kt += 16) {
        #pragma unroll
        for (int i = 0; i < 4; i++) {
            int lin = tid + i * 128;
            int r = lin >> 2;
            int kq = (lin & 3) * 4;
            float4 av = *(const float4*)&Ab[(size_t)(i0 + r) * Nc + kt + kq];
            As[kq + 0][r] = av.x; As[kq + 1][r] = av.y;
            As[kq + 2][r] = av.z; As[kq + 3][r] = av.w;
        }
        #pragma unroll
        for (int i = 0; i < 2; i++) {
            int lin = tid + i * 128;
            int r = lin >> 4;
            int cq = (lin & 15) * 4;
            *(float4*)&Vs[r][cq] = *(const float4*)&Vb[(size_t)(kt + r) * Dc + cq];
        }
        __syncthreads();
        #pragma unroll
        for (int kk = 0; kk < 16; kk++) {
            float a[8], bv[8];
            *(float4*)&a[0]  = *(const float4*)&As[kk][tr * 8];
            *(float4*)&a[4]  = *(const float4*)&As[kk][tr * 8 + 4];
            *(float4*)&bv[0] = *(const float4*)&Vs[kk][tc * 8];
            *(float4*)&bv[4] = *(const float4*)&Vs[kk][tc * 8 + 4];
            #pragma unroll
            for (int i = 0; i < 8; i++)
                #pragma unroll
                for (int j = 0; j < 8; j++)
                    acc[i][j] = fmaf(a[i], bv[j], acc[i][j]);
        }
        __syncthreads();
    }

    #pragma unroll
    for (int i = 0; i < 8; i++) {
        const int r = i0 + tr * 8 + i;
        float* dst = &Vt[(size_t)(b * Nc + r) * Dc + h * HDc + tc * 8];
        *(float4*)&dst[0] = *(float4*)&acc[i][0];
        *(float4*)&dst[4] = *(float4*)&acc[i][4];
    }
}

// ---------------------------------------------------------------------------
extern "C" void kernel_launch(void* const* d_in, const int* in_sizes, int n_in,
                              void* d_out, int out_size) {
    const float* query = (const float*)d_in[0];
    const float* key   = (const float*)d_in[1];
    const float* value = (const float*)d_in[2];
    const float* Wq = (const float*)d_in[3];
    const float* bq = (const float*)d_in[4];
    const float* Wk = (const float*)d_in[5];
    const float* bk = (const float*)d_in[6];
    const float* Wv = (const float*)d_in[7];
    const float* bv = (const float*)d_in[8];
    const float* Wo = (const float*)d_in[9];
    const float* bo = (const float*)d_in[10];

    float* out = (float*)d_out;              // [B, N, D]
    float* A   = (float*)d_out + OUT_ELEMS;  // [B, H, N, N]

    float* Q;  cudaGetSymbolAddress((void**)&Q,  g_Q);
    float* K;  cudaGetSymbolAddress((void**)&K,  g_K);
    float* V;  cudaGetSymbolAddress((void**)&V,  g_V);
    float* Vt; cudaGetSymbolAddress((void**)&Vt, g_Vt);

    // QKV projections: [4096,1024] @ [1024,1024]^T + b
    dim3 gProj(Dc / 128, MROWS / 128);
    gemm_nt_bias<<<gProj, 256>>>(query, Wq, bq, Q, Dc, Dc);
    gemm_nt_bias<<<gProj, 256>>>(key,   Wk, bk, K, Dc, Dc);
    gemm_nt_bias<<<gProj, 256>>>(value, Wv, bv, V, Dc, Dc);

    // A = scale * Q K^T
    dim3 gQK(Nc / 128, Nc / 128, BH);
    qk128<<<gQK, 256>>>(Q, K, A);

    // softmax rows (in place on A output)
    softmax_kernel<<<BH * Nc, 256>>>(A);

    // Vt = A V
    dim3 gAV(Nc / 128, BH);
    av128<<<gAV, 128>>>(A, V, Vt);

    // out = Vt @ Wo^T + bo
    gemm_nt_bias<<<gProj, 256>>>(Vt, Wo, bo, out, Dc, Dc);
}

// round 9
// speedup vs baseline: 1.0001x; 1.0001x over previous
#include <cuda_runtime.h>
#include <cuda_bf16.h>
#include <math.h>

// Problem constants
#define Bc 2
#define Nc 2048
#define Dc 1024
#define Hc 16
#define HDc 64
#define BH (Bc * Hc)          // 32
#define MROWS (Bc * Nc)       // 4096
#define OUT_ELEMS ((size_t)Bc * Nc * Dc)              // 4,194,304

// Scratch (static device memory — no runtime allocation)
__device__ float g_Q[MROWS * Dc];
__device__ float g_K[MROWS * Dc];
__device__ float g_V[MROWS * Dc];
__device__ float g_Vt[MROWS * Dc];

#define SM_PAD 132   // 128 + 4 pad, keeps float4 alignment (132*4 % 16 == 0)

// ---------------------------------------------------------------------------
// Projection GEMM: C[M,N] = X[M,K] @ W[N,K]^T + bias   (row-major)
// 128x128 tile, BK=16, 256 threads, 8x8 per thread.
// grid = (N/128, M/128)
// ---------------------------------------------------------------------------
__global__ void gemm_nt_bias(const float* __restrict__ X, const float* __restrict__ W,
                             const float* __restrict__ bias, float* __restrict__ C,
                             int K, int N) {
    __shared__ float As[16][SM_PAD];
    __shared__ float Bs[16][SM_PAD];
    const int tid = threadIdx.x;                 // 256
    const int row0 = blockIdx.y * 128;
    const int col0 = blockIdx.x * 128;
    const int tr = tid >> 4, tc = tid & 15;

    float acc[8][8] = {};

    for (int kt = 0; kt < K; kt += 16) {
        #pragma unroll
        for (int i = 0; i < 2; i++) {
            int lin = tid + i * 256;
            int r = lin >> 2;
            int kq = (lin & 3) * 4;
            float4 xa = *(const float4*)&X[(size_t)(row0 + r) * K + kt + kq];
            float4 wb = *(const float4*)&W[(size_t)(col0 + r) * K + kt + kq];
            As[kq + 0][r] = xa.x; As[kq + 1][r] = xa.y;
            As[kq + 2][r] = xa.z; As[kq + 3][r] = xa.w;
            Bs[kq + 0][r] = wb.x; Bs[kq + 1][r] = wb.y;
            Bs[kq + 2][r] = wb.z; Bs[kq + 3][r] = wb.w;
        }
        __syncthreads();
        #pragma unroll
        for (int kk = 0; kk < 16; kk++) {
            float a[8], b[8];
            *(float4*)&a[0] = *(const float4*)&As[kk][tr * 8];
            *(float4*)&a[4] = *(const float4*)&As[kk][tr * 8 + 4];
            *(float4*)&b[0] = *(const float4*)&Bs[kk][tc * 8];
            *(float4*)&b[4] = *(const float4*)&Bs[kk][tc * 8 + 4];
            #pragma unroll
            for (int i = 0; i < 8; i++)
                #pragma unroll
                for (int j = 0; j < 8; j++)
                    acc[i][j] = fmaf(a[i], b[j], acc[i][j]);
        }
        __syncthreads();
    }

    #pragma unroll
    for (int i = 0; i < 8; i++) {
        const int r = row0 + tr * 8 + i;
        float* dst = &C[(size_t)r * N + col0 + tc * 8];
        #pragma unroll
        for (int j = 0; j < 8; j++)
            dst[j] = acc[i][j] + bias[col0 + tc * 8 + j];
    }
}

// ---------------------------------------------------------------------------
// A = scale * Q_h @ K_h^T per (b,h).  128x128 tile, K=64 (BK=16, 4 iters).
// grid = (16, 16, 32)
// ---------------------------------------------------------------------------
__global__ void qk128(const float* __restrict__ Q, const float* __restrict__ K,
                      float* __restrict__ A) {
    __shared__ float Qs[16][SM_PAD];
    __shared__ float Ks[16][SM_PAD];
    const int bh = blockIdx.z;
    const int b = bh >> 4, h = bh & 15;
    const int i0 = blockIdx.y * 128;
    const int j0 = blockIdx.x * 128;
    const int tid = threadIdx.x;
    const int tr = tid >> 4, tc = tid & 15;

    const float* Qb = Q + (size_t)b * Nc * Dc + h * HDc;
    const float* Kb = K + (size_t)b * Nc * Dc + h * HDc;

    float acc[8][8] = {};

    for (int kt = 0; kt < HDc; kt += 16) {
        #pragma unroll
        for (int i = 0; i < 2; i++) {
            int lin = tid + i * 256;
            int r = lin >> 2;
            int kq = (lin & 3) * 4;
            float4 qv = *(const float4*)&Qb[(size_t)(i0 + r) * Dc + kt + kq];
            float4 kv = *(const float4*)&Kb[(size_t)(j0 + r) * Dc + kt + kq];
            Qs[kq + 0][r] = qv.x; Qs[kq + 1][r] = qv.y;
            Qs[kq + 2][r] = qv.z; Qs[kq + 3][r] = qv.w;
            Ks[kq + 0][r] = kv.x; Ks[kq + 1][r] = kv.y;
            Ks[kq + 2][r] = kv.z; Ks[kq + 3][r] = kv.w;
        }
        __syncthreads();
        #pragma unroll
        for (int kk = 0; kk < 16; kk++) {
            float a[8], bv[8];
            *(float4*)&a[0]  = *(const float4*)&Qs[kk][tr * 8];
            *(float4*)&a[4]  = *(const float4*)&Qs[kk][tr * 8 + 4];
            *(float4*)&bv[0] = *(const float4*)&Ks[kk][tc * 8];
            *(float4*)&bv[4] = *(const float4*)&Ks[kk][tc * 8 + 4];
            #pragma unroll
            for (int i = 0; i < 8; i++)
                #pragma unroll
                for (int j = 0; j < 8; j++)
                    acc[i][j] = fmaf(a[i], bv[j], acc[i][j]);
        }
        __syncthreads();
    }

    const float scale = 0.125f;
    float* Ab = A + (size_t)bh * Nc * Nc;
    #pragma unroll
    for (int i = 0; i < 8; i++) {
        const int r = i0 + tr * 8 + i;
        float4 v0, v1;
        v0.x = acc[i][0] * scale; v0.y = acc[i][1] * scale;
        v0.z = acc[i][2] * scale; v0.w = acc[i][3] * scale;
        v1.x = acc[i][4] * scale; v1.y = acc[i][5] * scale;
        v1.z = acc[i][6] * scale; v1.w = acc[i][7] * scale;
        *(float4*)&Ab[(size_t)r * Nc + j0 + tc * 8]     = v0;
        *(float4*)&Ab[(size_t)r * Nc + j0 + tc * 8 + 4] = v1;
    }
}

// ---------------------------------------------------------------------------
// Row softmax in place, register-resident (8 floats/thread). 256 threads/row.
// ---------------------------------------------------------------------------
__global__ void softmax_kernel(float* __restrict__ A) {
    __shared__ float red[256];
    float4* p = (float4*)(A + (size_t)blockIdx.x * Nc);  // 512 float4
    const int t = threadIdx.x;

    float4 v0 = p[t];
    float4 v1 = p[t + 256];

    float m = fmaxf(fmaxf(fmaxf(v0.x, v0.y), fmaxf(v0.z, v0.w)),
                    fmaxf(fmaxf(v1.x, v1.y), fmaxf(v1.z, v1.w)));
    red[t] = m;
    __syncthreads();
    #pragma unroll
    for (int s = 128; s > 0; s >>= 1) {
        if (t < s) red[t] = fmaxf(red[t], red[t + s]);
        __syncthreads();
    }
    const float mx = red[0];
    __syncthreads();

    v0.x = __expf(v0.x - mx); v0.y = __expf(v0.y - mx);
    v0.z = __expf(v0.z - mx); v0.w = __expf(v0.w - mx);
    v1.x = __expf(v1.x - mx); v1.y = __expf(v1.y - mx);
    v1.z = __expf(v1.z - mx); v1.w = __expf(v1.w - mx);

    float sum = (v0.x + v0.y + v0.z + v0.w) + (v1.x + v1.y + v1.z + v1.w);
    red[t] = sum;
    __syncthreads();
    #pragma unroll
    for (int s = 128; s > 0; s >>= 1) {
        if (t < s) red[t] += red[t + s];
        __syncthreads();
    }
    const float inv = 1.f / red[0];

    v0.x *= inv; v0.y *= inv; v0.z *= inv; v0.w *= inv;
    v1.x *= inv; v1.y *= inv; v1.z *= inv; v1.w *= inv;
    p[t] = v0;
    p[t + 256] = v1;
}

// ---------------------------------------------------------------------------
// Vt = A @ V_h per (b,h), head-interleaved output. 128x64 tile, BK=16,
// 128 threads, 8x8 per thread. grid = (16, 32)
// ---------------------------------------------------------------------------
__global__ void av128(const float* __restrict__ A, const float* __restrict__ V,
                      float* __restrict__ Vt) {
    __shared__ float As[16][SM_PAD];
    __shared__ float Vs[16][64];
    const int bh = blockIdx.y;
    const int b = bh >> 4, h = bh & 15;
    const int i0 = blockIdx.x * 128;
    const int tid = threadIdx.x;                 // 128
    const int tr = tid >> 3, tc = tid & 7;       // 16 x 8

    const float* Ab = A + (size_t)bh * Nc * Nc;
    const float* Vb = V + (size_t)b * Nc * Dc + h * HDc;

    float acc[8][8] = {};

    for (int kt = 0; kt < Nc; kt += 16) {
        #pragma unroll
        for (int i = 0; i < 4; i++) {
            int lin = tid + i * 128;
            int r = lin >> 2;
            int kq = (lin & 3) * 4;
            float4 av = *(const float4*)&Ab[(size_t)(i0 + r) * Nc + kt + kq];
            As[kq + 0][r] = av.x; As[kq + 1][r] = av.y;
            As[kq + 2][r] = av.z; As[kq + 3][r] = av.w;
        }
        #pragma unroll
        for (int i = 0; i < 2; i++) {
            int lin = tid + i * 128;
            int r = lin >> 4;
            int cq = (lin & 15) * 4;
            *(float4*)&Vs[r][cq] = *(const float4*)&Vb[(size_t)(kt + r) * Dc + cq];
        }
        __syncthreads();
        #pragma unroll
        for (int kk = 0; kk < 16; kk++) {
            float a[8], bv[8];
            *(float4*)&a[0]  = *(const float4*)&As[kk][tr * 8];
            *(float4*)&a[4]  = *(const float4*)&As[kk][tr * 8 + 4];
            *(float4*)&bv[0] = *(const float4*)&Vs[kk][tc * 8];
            *(float4*)&bv[4] = *(const float4*)&Vs[kk][tc * 8 + 4];
            #pragma unroll
            for (int i = 0; i < 8; i++)
                #pragma unroll
                for (int j = 0; j < 8; j++)
                    acc[i][j] = fmaf(a[i], bv[j], acc[i][j]);
        }
        __syncthreads();
    }

    #pragma unroll
    for (int i = 0; i < 8; i++) {
        const int r = i0 + tr * 8 + i;
        float* dst = &Vt[(size_t)(b * Nc + r) * Dc + h * HDc + tc * 8];
        *(float4*)&dst[0] = *(float4*)&acc[i][0];
        *(float4*)&dst[4] = *(float4*)&acc[i][4];
    }
}

// ---------------------------------------------------------------------------
extern "C" void kernel_launch(void* const* d_in, const int* in_sizes, int n_in,
                              void* d_out, int out_size) {
    const float* query = (const float*)d_in[0];
    const float* key   = (const float*)d_in[1];
    const float* value = (const float*)d_in[2];
    const float* Wq = (const float*)d_in[3];
    const float* bq = (const float*)d_in[4];
    const float* Wk = (const float*)d_in[5];
    const float* bk = (const float*)d_in[6];
    const float* Wv = (const float*)d_in[7];
    const float* bv = (const float*)d_in[8];
    const float* Wo = (const float*)d_in[9];
    const float* bo = (const float*)d_in[10];

    float* out = (float*)d_out;              // [B, N, D]
    float* A   = (float*)d_out + OUT_ELEMS;  // [B, H, N, N]

    float* Q;  cudaGetSymbolAddress((void**)&Q,  g_Q);
    float* K;  cudaGetSymbolAddress((void**)&K,  g_K);
    float* V;  cudaGetSymbolAddress((void**)&V,  g_V);
    float* Vt; cudaGetSymbolAddress((void**)&Vt, g_Vt);

    // QKV projections: [4096,1024] @ [1024,1024]^T + b
    dim3 gProj(Dc / 128, MROWS / 128);
    gemm_nt_bias<<<gProj, 256>>>(query, Wq, bq, Q, Dc, Dc);
    gemm_nt_bias<<<gProj, 256>>>(key,   Wk, bk, K, Dc, Dc);
    gemm_nt_bias<<<gProj, 256>>>(value, Wv, bv, V, Dc, Dc);

    // A = scale * Q K^T
    dim3 gQK(Nc / 128, Nc / 128, BH);
    qk128<<<gQK, 256>>>(Q, K, A);

    // softmax rows (in place on A output)
    softmax_kernel<<<BH * Nc, 256>>>(A);

    // Vt = A V
    dim3 gAV(Nc / 128, BH);
    av128<<<gAV, 128>>>(A, V, Vt);

    // out = Vt @ Wo^T + bo
    gemm_nt_bias<<<gProj, 256>>>(Vt, Wo, bo, out, Dc, Dc);
}

// round 15
// speedup vs baseline: 1.2088x; 1.2087x over previous
#include <cuda_runtime.h>
#include <cuda_bf16.h>
#include <stdint.h>

// Problem constants
#define Bc 2
#define Nc 2048
#define Dc 1024
#define Hc 16
#define HDc 64
#define BH (Bc * Hc)          // 32
#define MROWS (Bc * Nc)       // 4096
#define OUT_ELEMS ((size_t)Bc * Nc * Dc)

// Scratch (static device memory — no runtime allocation)
__device__ float g_Q[MROWS * Dc];
__device__ float g_K[MROWS * Dc];
__device__ float g_V[MROWS * Dc];
__device__ float g_Vt[MROWS * Dc];

// Tile row stride: 64 bf16 payload padded to 72 bf16 (144 B). 144 % 128 = 16,
// so 8 consecutive ldmatrix row addresses hit 8 distinct 16B bank groups.
#define TSB 144

// ---------------------------------------------------------------------------
// helpers
// ---------------------------------------------------------------------------
__device__ __forceinline__ uint32_t smem_u32(const void* p) {
    uint32_t a;
    asm("{ .reg .u64 t; cvta.to.shared.u64 t, %1; cvt.u32.u64 %0, t; }" : "=r"(a) : "l"(p));
    return a;
}
__device__ __forceinline__ void ldsm4(uint32_t* r, uint32_t addr) {
    asm volatile("ldmatrix.sync.aligned.m8n8.x4.shared.b16 {%0,%1,%2,%3}, [%4];"
                 : "=r"(r[0]), "=r"(r[1]), "=r"(r[2]), "=r"(r[3]) : "r"(addr));
}
__device__ __forceinline__ void ldsm2(uint32_t* r, uint32_t addr) {
    asm volatile("ldmatrix.sync.aligned.m8n8.x2.shared.b16 {%0,%1}, [%2];"
                 : "=r"(r[0]), "=r"(r[1]) : "r"(addr));
}
__device__ __forceinline__ void mma16816(float* d, const uint32_t* a, const uint32_t* b) {
    asm volatile("mma.sync.aligned.m16n8k16.row.col.f32.bf16.bf16.f32 "
                 "{%0,%1,%2,%3}, {%4,%5,%6,%7}, {%8,%9}, {%0,%1,%2,%3};"
                 : "+f"(d[0]), "+f"(d[1]), "+f"(d[2]), "+f"(d[3])
                 : "r"(a[0]), "r"(a[1]), "r"(a[2]), "r"(a[3]), "r"(b[0]), "r"(b[1]));
}

// fp32 -> (hi, lo) bf16 split, 8 elements, packed as 4x uint32 (bf16x2)
__device__ __forceinline__ void cvt8(const float* f, uint32_t* hi2, uint32_t* lo2) {
    #pragma unroll
    for (int i = 0; i < 4; i++) {
        float x0 = f[2 * i], x1 = f[2 * i + 1];
        __nv_bfloat16 h0 = __float2bfloat16_rn(x0);
        __nv_bfloat16 h1 = __float2bfloat16_rn(x1);
        float r0 = x0 - __bfloat162float(h0);
        float r1 = x1 - __bfloat162float(h1);
        __nv_bfloat16 l0 = __float2bfloat16_rn(r0);
        __nv_bfloat16 l1 = __float2bfloat16_rn(r1);
        uint32_t ha = *(const uint16_t*)&h0, hb = *(const uint16_t*)&h1;
        uint32_t la = *(const uint16_t*)&l0, lb = *(const uint16_t*)&l1;
        hi2[i] = ha | (hb << 16);
        lo2[i] = la | (lb << 16);
    }
}

// Fill a [rows x 64] bf16 hi/lo tile pair (row stride TSB) from fp32 global.
__device__ __forceinline__ void fill_hilo(char* hi, char* lo, const float* g,
                                          int ldg, int rows, int tid) {
    const int units = rows * 8;
    for (int u = tid; u < units; u += 256) {
        int r = u >> 3, s = u & 7;
        const float* p = g + (size_t)r * ldg + s * 8;
        float f[8];
        *(float4*)&f[0] = *(const float4*)&p[0];
        *(float4*)&f[4] = *(const float4*)&p[4];
        uint32_t h[4], l[4];
        cvt8(f, h, l);
        const int off = r * TSB + s * 16;
        *(uint4*)(hi + off) = make_uint4(h[0], h[1], h[2], h[3]);
        *(uint4*)(lo + off) = make_uint4(l[0], l[1], l[2], l[3]);
    }
}

// One 64-deep K chunk of hi/lo MMAs. acc[MT][NT][4].
template <int MT, int NT>
__device__ __forceinline__ void mma_chunk(uint32_t aHi, uint32_t aLo,
                                          uint32_t bHi, uint32_t bLo,
                                          int warp_m, int warp_n, int lane,
                                          float acc[MT][NT][4]) {
    #pragma unroll
    for (int k16 = 0; k16 < 4; k16++) {
        uint32_t ah[MT][4], al[MT][4], bh[NT][2], bl[NT][2];
        const int acol = k16 * 16 + (lane >> 4) * 8;
        #pragma unroll
        for (int mt = 0; mt < MT; mt++) {
            const uint32_t off = (uint32_t)(warp_m + mt * 16 + (lane & 15)) * TSB + acol * 2;
            ldsm4(ah[mt], aHi + off);
            ldsm4(al[mt], aLo + off);
        }
        const int l = lane & 15;
        const int bcol = k16 * 16 + (l >> 3) * 8;
        #pragma unroll
        for (int nt = 0; nt < NT; nt++) {
            const uint32_t off = (uint32_t)(warp_n + nt * 8 + (l & 7)) * TSB + bcol * 2;
            ldsm2(bh[nt], bHi + off);
            ldsm2(bl[nt], bLo + off);
        }
        #pragma unroll
        for (int mt = 0; mt < MT; mt++)
            #pragma unroll
            for (int nt = 0; nt < NT; nt++) {
                mma16816(acc[mt][nt], ah[mt], bh[nt]);
                mma16816(acc[mt][nt], ah[mt], bl[nt]);
                mma16816(acc[mt][nt], al[mt], bh[nt]);
            }
    }
}

// ---------------------------------------------------------------------------
// Projection GEMM: C[4096,1024] = X @ W^T + bias. 128x128 tile, K=1024.
// grid (8, 32), 256 threads. smem = 4 x 18432 = 73728 B.
// ---------------------------------------------------------------------------
__global__ void __launch_bounds__(256, 1)
proj_mma(const float* __restrict__ X, const float* __restrict__ W,
         const float* __restrict__ bias, float* __restrict__ C) {
    extern __shared__ char sm[];
    char* Ahi = sm;            char* Alo = sm + 18432;
    char* Bhi = sm + 36864;    char* Blo = sm + 55296;
    const uint32_t smb = smem_u32(sm);
    const uint32_t aHi = smb, aLo = smb + 18432, bHi = smb + 36864, bLo = smb + 55296;
    const int tid = threadIdx.x, wid = tid >> 5, lane = tid & 31;
    const int row0 = blockIdx.y * 128, col0 = blockIdx.x * 128;
    const int warp_m = (wid >> 2) * 64, warp_n = (wid & 3) * 32;

    float acc[4][4][4] = {};

    for (int c = 0; c < 16; c++) {
        const int kt = c * 64;
        fill_hilo(Ahi, Alo, X + (size_t)row0 * Dc + kt, Dc, 128, tid);
        fill_hilo(Bhi, Blo, W + (size_t)col0 * Dc + kt, Dc, 128, tid);
        __syncthreads();
        mma_chunk<4, 4>(aHi, aLo, bHi, bLo, warp_m, warp_n, lane, acc);
        __syncthreads();
    }

    #pragma unroll
    for (int mt = 0; mt < 4; mt++) {
        const int r = row0 + warp_m + mt * 16 + (lane >> 2);
        #pragma unroll
        for (int nt = 0; nt < 4; nt++) {
            const int col = col0 + warp_n + nt * 8 + (lane & 3) * 2;
            const float2 bb = *(const float2*)&bias[col];
            float2 o0 = make_float2(acc[mt][nt][0] + bb.x, acc[mt][nt][1] + bb.y);
            float2 o1 = make_float2(acc[mt][nt][2] + bb.x, acc[mt][nt][3] + bb.y);
            *(float2*)&C[(size_t)r * Dc + col]       = o0;
            *(float2*)&C[(size_t)(r + 8) * Dc + col] = o1;
        }
    }
}

// ---------------------------------------------------------------------------
// QK: A[bh,i,j] = 0.125 * Qh @ Kh^T. 128x128 tile, K=64 (1 chunk).
// grid (16, 16, 32), 256 threads.
// ---------------------------------------------------------------------------
__global__ void __launch_bounds__(256, 1)
qk_mma(const float* __restrict__ Q, const float* __restrict__ K, float* __restrict__ A) {
    extern __shared__ char sm[];
    char* Ahi = sm;            char* Alo = sm + 18432;
    char* Bhi = sm + 36864;    char* Blo = sm + 55296;
    const uint32_t smb = smem_u32(sm);
    const uint32_t aHi = smb, aLo = smb + 18432, bHi = smb + 36864, bLo = smb + 55296;
    const int tid = threadIdx.x, wid = tid >> 5, lane = tid & 31;
    const int bh = blockIdx.z, b = bh >> 4, h = bh & 15;
    const int i0 = blockIdx.y * 128, j0 = blockIdx.x * 128;
    const int warp_m = (wid >> 2) * 64, warp_n = (wid & 3) * 32;

    const float* Qb = Q + (size_t)(b * Nc + i0) * Dc + h * HDc;
    const float* Kb = K + (size_t)(b * Nc + j0) * Dc + h * HDc;

    float acc[4][4][4] = {};

    fill_hilo(Ahi, Alo, Qb, Dc, 128, tid);
    fill_hilo(Bhi, Blo, Kb, Dc, 128, tid);
    __syncthreads();
    mma_chunk<4, 4>(aHi, aLo, bHi, bLo, warp_m, warp_n, lane, acc);

    float* Ab = A + (size_t)bh * Nc * Nc;
    #pragma unroll
    for (int mt = 0; mt < 4; mt++) {
        const int r = i0 + warp_m + mt * 16 + (lane >> 2);
        #pragma unroll
        for (int nt = 0; nt < 4; nt++) {
            const int col = j0 + warp_n + nt * 8 + (lane & 3) * 2;
            float2 o0 = make_float2(acc[mt][nt][0] * 0.125f, acc[mt][nt][1] * 0.125f);
            float2 o1 = make_float2(acc[mt][nt][2] * 0.125f, acc[mt][nt][3] * 0.125f);
            *(float2*)&Ab[(size_t)r * Nc + col]       = o0;
            *(float2*)&Ab[(size_t)(r + 8) * Nc + col] = o1;
        }
    }
}

// ---------------------------------------------------------------------------
// Row softmax in place, register-resident. 256 threads/row.
// ---------------------------------------------------------------------------
__global__ void softmax_kernel(float* __restrict__ A) {
    __shared__ float red[256];
    float4* p = (float4*)(A + (size_t)blockIdx.x * Nc);
    const int t = threadIdx.x;

    float4 v0 = p[t];
    float4 v1 = p[t + 256];

    float m = fmaxf(fmaxf(fmaxf(v0.x, v0.y), fmaxf(v0.z, v0.w)),
                    fmaxf(fmaxf(v1.x, v1.y), fmaxf(v1.z, v1.w)));
    red[t] = m;
    __syncthreads();
    #pragma unroll
    for (int s = 128; s > 0; s >>= 1) {
        if (t < s) red[t] = fmaxf(red[t], red[t + s]);
        __syncthreads();
    }
    const float mx = red[0];
    __syncthreads();

    v0.x = __expf(v0.x - mx); v0.y = __expf(v0.y - mx);
    v0.z = __expf(v0.z - mx); v0.w = __expf(v0.w - mx);
    v1.x = __expf(v1.x - mx); v1.y = __expf(v1.y - mx);
    v1.z = __expf(v1.z - mx); v1.w = __expf(v1.w - mx);

    float sum = (v0.x + v0.y + v0.z + v0.w) + (v1.x + v1.y + v1.z + v1.w);
    red[t] = sum;
    __syncthreads();
    #pragma unroll
    for (int s = 128; s > 0; s >>= 1) {
        if (t < s) red[t] += red[t + s];
        __syncthreads();
    }
    const float inv = 1.f / red[0];

    v0.x *= inv; v0.y *= inv; v0.z *= inv; v0.w *= inv;
    v1.x *= inv; v1.y *= inv; v1.z *= inv; v1.w *= inv;
    p[t] = v0;
    p[t + 256] = v1;
}

// ---------------------------------------------------------------------------
// AV: Vt[b,i,h*64+d] = A[bh] @ V_h. 128(m) x 64(n) tile, K=2048 (32 chunks).
// V transposed during smem conversion so the MMA is NT.
// grid (16, 32), 256 threads. smem = 2x18432 + 2x9216 = 55296 B.
// ---------------------------------------------------------------------------
__global__ void __launch_bounds__(256, 1)
av_mma(const float* __restrict__ A, const float* __restrict__ V, float* __restrict__ Vt) {
    extern __shared__ char sm[];
    char* Ahi = sm;            char* Alo = sm + 18432;
    char* Bhi = sm + 36864;    char* Blo = sm + 46080;
    const uint32_t smb = smem_u32(sm);
    const uint32_t aHi = smb, aLo = smb + 18432, bHi = smb + 36864, bLo = smb + 46080;
    const int tid = threadIdx.x, wid = tid >> 5, lane = tid & 31;
    const int bh = blockIdx.y, b = bh >> 4, h = bh & 15;
    const int i0 = blockIdx.x * 128;
    const int warp_m = (wid >> 1) * 32, warp_n = (wid & 1) * 32;  // 4(m) x 2(n)

    const float* Ab = A + (size_t)bh * Nc * Nc + (size_t)i0 * Nc;
    const float* Vb = V + (size_t)b * Nc * Dc + h * HDc;

    float acc[2][4][4] = {};

    for (int c = 0; c < 32; c++) {
        const int j0 = c * 64;
        // A tile: 128 rows x 64 k
        fill_hilo(Ahi, Alo, Ab + j0, Nc, 128, tid);
        // V tile transposed: B[n=d][k=j] = V[j0+j][d]; 64 x 64
        for (int u = tid; u < 512; u += 256) {
            const int j = u & 63, s = u >> 6;
            const float* g = Vb + (size_t)(j0 + j) * Dc + s * 8;
            float f[8];
            *(float4*)&f[0] = *(const float4*)&g[0];
            *(float4*)&f[4] = *(const float4*)&g[4];
            #pragma unroll
            for (int e = 0; e < 8; e++) {
                const float x = f[e];
                __nv_bfloat16 hv = __float2bfloat16_rn(x);
                __nv_bfloat16 lv = __float2bfloat16_rn(x - __bfloat162float(hv));
                const int d = s * 8 + e;
                *(uint16_t*)(Bhi + d * TSB + j * 2) = *(const uint16_t*)&hv;
                *(uint16_t*)(Blo + d * TSB + j * 2) = *(const uint16_t*)&lv;
            }
        }
        __syncthreads();
        mma_chunk<2, 4>(aHi, aLo, bHi, bLo, warp_m, warp_n, lane, acc);
        __syncthreads();
    }

    #pragma unroll
    for (int mt = 0; mt < 2; mt++) {
        const int r = i0 + warp_m + mt * 16 + (lane >> 2);
        #pragma unroll
        for (int nt = 0; nt < 4; nt++) {
            const int d = warp_n + nt * 8 + (lane & 3) * 2;
            float* dst0 = &Vt[(size_t)(b * Nc + r) * Dc + h * HDc + d];
            float* dst1 = &Vt[(size_t)(b * Nc + r + 8) * Dc + h * HDc + d];
            *(float2*)dst0 = make_float2(acc[mt][nt][0], acc[mt][nt][1]);
            *(float2*)dst1 = make_float2(acc[mt][nt][2], acc[mt][nt][3]);
        }
    }
}

// ---------------------------------------------------------------------------
extern "C" void kernel_launch(void* const* d_in, const int* in_sizes, int n_in,
                              void* d_out, int out_size) {
    const float* query = (const float*)d_in[0];
    const float* key   = (const float*)d_in[1];
    const float* value = (const float*)d_in[2];
    const float* Wq = (const float*)d_in[3];
    const float* bq = (const float*)d_in[4];
    const float* Wk = (const float*)d_in[5];
    const float* bk = (const float*)d_in[6];
    const float* Wv = (const float*)d_in[7];
    const float* bv = (const float*)d_in[8];
    const float* Wo = (const float*)d_in[9];
    const float* bo = (const float*)d_in[10];

    float* out = (float*)d_out;              // [B, N, D]
    float* A   = (float*)d_out + OUT_ELEMS;  // [B, H, N, N]

    float* Q;  cudaGetSymbolAddress((void**)&Q,  g_Q);
    float* K;  cudaGetSymbolAddress((void**)&K,  g_K);
    float* V;  cudaGetSymbolAddress((void**)&V,  g_V);
    float* Vt; cudaGetSymbolAddress((void**)&Vt, g_Vt);

    const int SMEM_BIG = 4 * 18432;                 // 73728
    const int SMEM_AV  = 2 * 18432 + 2 * 9216;      // 55296
    cudaFuncSetAttribute(proj_mma, cudaFuncAttributeMaxDynamicSharedMemorySize, SMEM_BIG);
    cudaFuncSetAttribute(qk_mma,   cudaFuncAttributeMaxDynamicSharedMemorySize, SMEM_BIG);
    cudaFuncSetAttribute(av_mma,   cudaFuncAttributeMaxDynamicSharedMemorySize, SMEM_AV);

    dim3 gProj(Dc / 128, MROWS / 128);              // (8, 32)
    proj_mma<<<gProj, 256, SMEM_BIG>>>(query, Wq, bq, Q);
    proj_mma<<<gProj, 256, SMEM_BIG>>>(key,   Wk, bk, K);
    proj_mma<<<gProj, 256, SMEM_BIG>>>(value, Wv, bv, V);

    dim3 gQK(Nc / 128, Nc / 128, BH);               // (16, 16, 32)
    qk_mma<<<gQK, 256, SMEM_BIG>>>(Q, K, A);

    softmax_kernel<<<BH * Nc, 256>>>(A);

    dim3 gAV(Nc / 128, BH);                         // (16, 32)
    av_mma<<<gAV, 256, SMEM_AV>>>(A, V, Vt);

    proj_mma<<<gProj, 256, SMEM_BIG>>>(Vt, Wo, bo, out);
}

// round 16
// speedup vs baseline: 1.2100x; 1.0011x over previous
#include <cuda_runtime.h>
#include <cuda_bf16.h>
#include <stdint.h>

// Problem constants
#define Bc 2
#define Nc 2048
#define Dc 1024
#define Hc 16
#define HDc 64
#define BH (Bc * Hc)          // 32
#define MROWS (Bc * Nc)       // 4096
#define OUT_ELEMS ((size_t)Bc * Nc * Dc)

// Scratch (static device memory — no runtime allocation)
__device__ float g_Q[MROWS * Dc];
__device__ float g_K[MROWS * Dc];
__device__ float g_V[MROWS * Dc];
__device__ float g_Vt[MROWS * Dc];

// Tile row stride: 64 bf16 payload padded to 72 bf16 (144 B). 144 % 128 = 16,
// so 8 consecutive ldmatrix row addresses hit 8 distinct 16B bank groups.
#define TSB 144

// ---------------------------------------------------------------------------
// helpers
// ---------------------------------------------------------------------------
__device__ __forceinline__ uint32_t smem_u32(const void* p) {
    uint32_t a;
    asm("{ .reg .u64 t; cvta.to.shared.u64 t, %1; cvt.u32.u64 %0, t; }" : "=r"(a) : "l"(p));
    return a;
}
__device__ __forceinline__ void ldsm4(uint32_t* r, uint32_t addr) {
    asm volatile("ldmatrix.sync.aligned.m8n8.x4.shared.b16 {%0,%1,%2,%3}, [%4];"
                 : "=r"(r[0]), "=r"(r[1]), "=r"(r[2]), "=r"(r[3]) : "r"(addr));
}
__device__ __forceinline__ void ldsm2(uint32_t* r, uint32_t addr) {
    asm volatile("ldmatrix.sync.aligned.m8n8.x2.shared.b16 {%0,%1}, [%2];"
                 : "=r"(r[0]), "=r"(r[1]) : "r"(addr));
}
__device__ __forceinline__ void mma16816(float* d, const uint32_t* a, const uint32_t* b) {
    asm volatile("mma.sync.aligned.m16n8k16.row.col.f32.bf16.bf16.f32 "
                 "{%0,%1,%2,%3}, {%4,%5,%6,%7}, {%8,%9}, {%0,%1,%2,%3};"
                 : "+f"(d[0]), "+f"(d[1]), "+f"(d[2]), "+f"(d[3])
                 : "r"(a[0]), "r"(a[1]), "r"(a[2]), "r"(a[3]), "r"(b[0]), "r"(b[1]));
}

// fp32 -> (hi, lo) bf16 split, 8 elements, packed as 4x uint32 (bf16x2)
__device__ __forceinline__ void cvt8(const float* f, uint32_t* hi2, uint32_t* lo2) {
    #pragma unroll
    for (int i = 0; i < 4; i++) {
        float x0 = f[2 * i], x1 = f[2 * i + 1];
        __nv_bfloat16 h0 = __float2bfloat16_rn(x0);
        __nv_bfloat16 h1 = __float2bfloat16_rn(x1);
        float r0 = x0 - __bfloat162float(h0);
        float r1 = x1 - __bfloat162float(h1);
        __nv_bfloat16 l0 = __float2bfloat16_rn(r0);
        __nv_bfloat16 l1 = __float2bfloat16_rn(r1);
        uint32_t ha = *(const uint16_t*)&h0, hb = *(const uint16_t*)&h1;
        uint32_t la = *(const uint16_t*)&l0, lb = *(const uint16_t*)&l1;
        hi2[i] = ha | (hb << 16);
        lo2[i] = la | (lb << 16);
    }
}

// Fill a [rows x 64] bf16 hi/lo tile pair (row stride TSB) from fp32 global.
__device__ __forceinline__ void fill_hilo(char* hi, char* lo, const float* g,
                                          int ldg, int rows, int tid) {
    const int units = rows * 8;
    for (int u = tid; u < units; u += 256) {
        int r = u >> 3, s = u & 7;
        const float* p = g + (size_t)r * ldg + s * 8;
        float f[8];
        *(float4*)&f[0] = *(const float4*)&p[0];
        *(float4*)&f[4] = *(const float4*)&p[4];
        uint32_t h[4], l[4];
        cvt8(f, h, l);
        const int off = r * TSB + s * 16;
        *(uint4*)(hi + off) = make_uint4(h[0], h[1], h[2], h[3]);
        *(uint4*)(lo + off) = make_uint4(l[0], l[1], l[2], l[3]);
    }
}

// One 64-deep K chunk of hi/lo MMAs. acc[MT][NT][4].
template <int MT, int NT>
__device__ __forceinline__ void mma_chunk(uint32_t aHi, uint32_t aLo,
                                          uint32_t bHi, uint32_t bLo,
                                          int warp_m, int warp_n, int lane,
                                          float acc[MT][NT][4]) {
    #pragma unroll
    for (int k16 = 0; k16 < 4; k16++) {
        uint32_t ah[MT][4], al[MT][4], bh[NT][2], bl[NT][2];
        const int acol = k16 * 16 + (lane >> 4) * 8;
        #pragma unroll
        for (int mt = 0; mt < MT; mt++) {
            const uint32_t off = (uint32_t)(warp_m + mt * 16 + (lane & 15)) * TSB + acol * 2;
            ldsm4(ah[mt], aHi + off);
            ldsm4(al[mt], aLo + off);
        }
        const int l = lane & 15;
        const int bcol = k16 * 16 + (l >> 3) * 8;
        #pragma unroll
        for (int nt = 0; nt < NT; nt++) {
            const uint32_t off = (uint32_t)(warp_n + nt * 8 + (l & 7)) * TSB + bcol * 2;
            ldsm2(bh[nt], bHi + off);
            ldsm2(bl[nt], bLo + off);
        }
        #pragma unroll
        for (int mt = 0; mt < MT; mt++)
            #pragma unroll
            for (int nt = 0; nt < NT; nt++) {
                mma16816(acc[mt][nt], ah[mt], bh[nt]);
                mma16816(acc[mt][nt], ah[mt], bl[nt]);
                mma16816(acc[mt][nt], al[mt], bh[nt]);
            }
    }
}

// ---------------------------------------------------------------------------
// Projection GEMM: C[4096,1024] = X @ W^T + bias. 128x128 tile, K=1024.
// grid (8, 32), 256 threads. smem = 4 x 18432 = 73728 B.
// ---------------------------------------------------------------------------
__global__ void __launch_bounds__(256, 1)
proj_mma(const float* __restrict__ X, const float* __restrict__ W,
         const float* __restrict__ bias, float* __restrict__ C) {
    extern __shared__ char sm[];
    char* Ahi = sm;            char* Alo = sm + 18432;
    char* Bhi = sm + 36864;    char* Blo = sm + 55296;
    const uint32_t smb = smem_u32(sm);
    const uint32_t aHi = smb, aLo = smb + 18432, bHi = smb + 36864, bLo = smb + 55296;
    const int tid = threadIdx.x, wid = tid >> 5, lane = tid & 31;
    const int row0 = blockIdx.y * 128, col0 = blockIdx.x * 128;
    const int warp_m = (wid >> 2) * 64, warp_n = (wid & 3) * 32;

    float acc[4][4][4] = {};

    for (int c = 0; c < 16; c++) {
        const int kt = c * 64;
        fill_hilo(Ahi, Alo, X + (size_t)row0 * Dc + kt, Dc, 128, tid);
        fill_hilo(Bhi, Blo, W + (size_t)col0 * Dc + kt, Dc, 128, tid);
        __syncthreads();
        mma_chunk<4, 4>(aHi, aLo, bHi, bLo, warp_m, warp_n, lane, acc);
        __syncthreads();
    }

    #pragma unroll
    for (int mt = 0; mt < 4; mt++) {
        const int r = row0 + warp_m + mt * 16 + (lane >> 2);
        #pragma unroll
        for (int nt = 0; nt < 4; nt++) {
            const int col = col0 + warp_n + nt * 8 + (lane & 3) * 2;
            const float2 bb = *(const float2*)&bias[col];
            float2 o0 = make_float2(acc[mt][nt][0] + bb.x, acc[mt][nt][1] + bb.y);
            float2 o1 = make_float2(acc[mt][nt][2] + bb.x, acc[mt][nt][3] + bb.y);
            *(float2*)&C[(size_t)r * Dc + col]       = o0;
            *(float2*)&C[(size_t)(r + 8) * Dc + col] = o1;
        }
    }
}

// ---------------------------------------------------------------------------
// QK: A[bh,i,j] = 0.125 * Qh @ Kh^T. 128x128 tile, K=64 (1 chunk).
// grid (16, 16, 32), 256 threads.
// ---------------------------------------------------------------------------
__global__ void __launch_bounds__(256, 1)
qk_mma(const float* __restrict__ Q, const float* __restrict__ K, float* __restrict__ A) {
    extern __shared__ char sm[];
    char* Ahi = sm;            char* Alo = sm + 18432;
    char* Bhi = sm + 36864;    char* Blo = sm + 55296;
    const uint32_t smb = smem_u32(sm);
    const uint32_t aHi = smb, aLo = smb + 18432, bHi = smb + 36864, bLo = smb + 55296;
    const int tid = threadIdx.x, wid = tid >> 5, lane = tid & 31;
    const int bh = blockIdx.z, b = bh >> 4, h = bh & 15;
    const int i0 = blockIdx.y * 128, j0 = blockIdx.x * 128;
    const int warp_m = (wid >> 2) * 64, warp_n = (wid & 3) * 32;

    const float* Qb = Q + (size_t)(b * Nc + i0) * Dc + h * HDc;
    const float* Kb = K + (size_t)(b * Nc + j0) * Dc + h * HDc;

    float acc[4][4][4] = {};

    fill_hilo(Ahi, Alo, Qb, Dc, 128, tid);
    fill_hilo(Bhi, Blo, Kb, Dc, 128, tid);
    __syncthreads();
    mma_chunk<4, 4>(aHi, aLo, bHi, bLo, warp_m, warp_n, lane, acc);

    float* Ab = A + (size_t)bh * Nc * Nc;
    #pragma unroll
    for (int mt = 0; mt < 4; mt++) {
        const int r = i0 + warp_m + mt * 16 + (lane >> 2);
        #pragma unroll
        for (int nt = 0; nt < 4; nt++) {
            const int col = j0 + warp_n + nt * 8 + (lane & 3) * 2;
            float2 o0 = make_float2(acc[mt][nt][0] * 0.125f, acc[mt][nt][1] * 0.125f);
            float2 o1 = make_float2(acc[mt][nt][2] * 0.125f, acc[mt][nt][3] * 0.125f);
            *(float2*)&Ab[(size_t)r * Nc + col]       = o0;
            *(float2*)&Ab[(size_t)(r + 8) * Nc + col] = o1;
        }
    }
}

// ---------------------------------------------------------------------------
// Row softmax in place, register-resident. 256 threads/row.
// ---------------------------------------------------------------------------
__global__ void softmax_kernel(float* __restrict__ A) {
    __shared__ float red[256];
    float4* p = (float4*)(A + (size_t)blockIdx.x * Nc);
    const int t = threadIdx.x;

    float4 v0 = p[t];
    float4 v1 = p[t + 256];

    float m = fmaxf(fmaxf(fmaxf(v0.x, v0.y), fmaxf(v0.z, v0.w)),
                    fmaxf(fmaxf(v1.x, v1.y), fmaxf(v1.z, v1.w)));
    red[t] = m;
    __syncthreads();
    #pragma unroll
    for (int s = 128; s > 0; s >>= 1) {
        if (t < s) red[t] = fmaxf(red[t], red[t + s]);
        __syncthreads();
    }
    const float mx = red[0];
    __syncthreads();

    v0.x = __expf(v0.x - mx); v0.y = __expf(v0.y - mx);
    v0.z = __expf(v0.z - mx); v0.w = __expf(v0.w - mx);
    v1.x = __expf(v1.x - mx); v1.y = __expf(v1.y - mx);
    v1.z = __expf(v1.z - mx); v1.w = __expf(v1.w - mx);

    float sum = (v0.x + v0.y + v0.z + v0.w) + (v1.x + v1.y + v1.z + v1.w);
    red[t] = sum;
    __syncthreads();
    #pragma unroll
    for (int s = 128; s > 0; s >>= 1) {
        if (t < s) red[t] += red[t + s];
        __syncthreads();
    }
    const float inv = 1.f / red[0];

    v0.x *= inv; v0.y *= inv; v0.z *= inv; v0.w *= inv;
    v1.x *= inv; v1.y *= inv; v1.z *= inv; v1.w *= inv;
    p[t] = v0;
    p[t + 256] = v1;
}

// ---------------------------------------------------------------------------
// AV: Vt[b,i,h*64+d] = A[bh] @ V_h. 128(m) x 64(n) tile, K=2048 (32 chunks).
// V transposed during smem conversion so the MMA is NT.
// grid (16, 32), 256 threads. smem = 2x18432 + 2x9216 = 55296 B.
// ---------------------------------------------------------------------------
__global__ void __launch_bounds__(256, 1)
av_mma(const float* __restrict__ A, const float* __restrict__ V, float* __restrict__ Vt) {
    extern __shared__ char sm[];
    char* Ahi = sm;            char* Alo = sm + 18432;
    char* Bhi = sm + 36864;    char* Blo = sm + 46080;
    const uint32_t smb = smem_u32(sm);
    const uint32_t aHi = smb, aLo = smb + 18432, bHi = smb + 36864, bLo = smb + 46080;
    const int tid = threadIdx.x, wid = tid >> 5, lane = tid & 31;
    const int bh = blockIdx.y, b = bh >> 4, h = bh & 15;
    const int i0 = blockIdx.x * 128;
    const int warp_m = (wid >> 1) * 32, warp_n = (wid & 1) * 32;  // 4(m) x 2(n)

    const float* Ab = A + (size_t)bh * Nc * Nc + (size_t)i0 * Nc;
    const float* Vb = V + (size_t)b * Nc * Dc + h * HDc;

    float acc[2][4][4] = {};

    for (int c = 0; c < 32; c++) {
        const int j0 = c * 64;
        // A tile: 128 rows x 64 k
        fill_hilo(Ahi, Alo, Ab + j0, Nc, 128, tid);
        // V tile transposed: B[n=d][k=j] = V[j0+j][d]; 64 x 64
        for (int u = tid; u < 512; u += 256) {
            const int j = u & 63, s = u >> 6;
            const float* g = Vb + (size_t)(j0 + j) * Dc + s * 8;
            float f[8];
            *(float4*)&f[0] = *(const float4*)&g[0];
            *(float4*)&f[4] = *(const float4*)&g[4];
            #pragma unroll
            for (int e = 0; e < 8; e++) {
                const float x = f[e];
                __nv_bfloat16 hv = __float2bfloat16_rn(x);
                __nv_bfloat16 lv = __float2bfloat16_rn(x - __bfloat162float(hv));
                const int d = s * 8 + e;
                *(uint16_t*)(Bhi + d * TSB + j * 2) = *(const uint16_t*)&hv;
                *(uint16_t*)(Blo + d * TSB + j * 2) = *(const uint16_t*)&lv;
            }
        }
        __syncthreads();
        mma_chunk<2, 4>(aHi, aLo, bHi, bLo, warp_m, warp_n, lane, acc);
        __syncthreads();
    }

    #pragma unroll
    for (int mt = 0; mt < 2; mt++) {
        const int r = i0 + warp_m + mt * 16 + (lane >> 2);
        #pragma unroll
        for (int nt = 0; nt < 4; nt++) {
            const int d = warp_n + nt * 8 + (lane & 3) * 2;
            float* dst0 = &Vt[(size_t)(b * Nc + r) * Dc + h * HDc + d];
            float* dst1 = &Vt[(size_t)(b * Nc + r + 8) * Dc + h * HDc + d];
            *(float2*)dst0 = make_float2(acc[mt][nt][0], acc[mt][nt][1]);
            *(float2*)dst1 = make_float2(acc[mt][nt][2], acc[mt][nt][3]);
        }
    }
}

// ---------------------------------------------------------------------------
extern "C" void kernel_launch(void* const* d_in, const int* in_sizes, int n_in,
                              void* d_out, int out_size) {
    const float* query = (const float*)d_in[0];
    const float* key   = (const float*)d_in[1];
    const float* value = (const float*)d_in[2];
    const float* Wq = (const float*)d_in[3];
    const float* bq = (const float*)d_in[4];
    const float* Wk = (const float*)d_in[5];
    const float* bk = (const float*)d_in[6];
    const float* Wv = (const float*)d_in[7];
    const float* bv = (const float*)d_in[8];
    const float* Wo = (const float*)d_in[9];
    const float* bo = (const float*)d_in[10];

    float* out = (float*)d_out;              // [B, N, D]
    float* A   = (float*)d_out + OUT_ELEMS;  // [B, H, N, N]

    float* Q;  cudaGetSymbolAddress((void**)&Q,  g_Q);
    float* K;  cudaGetSymbolAddress((void**)&K,  g_K);
    float* V;  cudaGetSymbolAddress((void**)&V,  g_V);
    float* Vt; cudaGetSymbolAddress((void**)&Vt, g_Vt);

    const int SMEM_BIG = 4 * 18432;                 // 73728
    const int SMEM_AV  = 2 * 18432 + 2 * 9216;      // 55296
    cudaFuncSetAttribute(proj_mma, cudaFuncAttributeMaxDynamicSharedMemorySize, SMEM_BIG);
    cudaFuncSetAttribute(qk_mma,   cudaFuncAttributeMaxDynamicSharedMemorySize, SMEM_BIG);
    cudaFuncSetAttribute(av_mma,   cudaFuncAttributeMaxDynamicSharedMemorySize, SMEM_AV);

    dim3 gProj(Dc / 128, MROWS / 128);              // (8, 32)
    proj_mma<<<gProj, 256, SMEM_BIG>>>(query, Wq, bq, Q);
    proj_mma<<<gProj, 256, SMEM_BIG>>>(key,   Wk, bk, K);
    proj_mma<<<gProj, 256, SMEM_BIG>>>(value, Wv, bv, V);

    dim3 gQK(Nc / 128, Nc / 128, BH);               // (16, 16, 32)
    qk_mma<<<gQK, 256, SMEM_BIG>>>(Q, K, A);

    softmax_kernel<<<BH * Nc, 256>>>(A);

    dim3 gAV(Nc / 128, BH);                         // (16, 32)
    av_mma<<<gAV, 256, SMEM_AV>>>(A, V, Vt);

    proj_mma<<<gProj, 256, SMEM_BIG>>>(Vt, Wo, bo, out);
}

// round 17
// speedup vs baseline: 1.5353x; 1.2688x over previous
#include <cuda_runtime.h>
#include <cuda_bf16.h>
#include <stdint.h>

// Problem constants
#define Bc 2
#define Nc 2048
#define Dc 1024
#define Hc 16
#define HDc 64
#define BH (Bc * Hc)          // 32
#define MROWS (Bc * Nc)       // 4096
#define OUT_ELEMS ((size_t)Bc * Nc * Dc)

// Scratch (static device memory — no runtime allocation)
__device__ float g_Q[MROWS * Dc];
__device__ float g_K[MROWS * Dc];
__device__ float g_V[MROWS * Dc];
__device__ float g_Vt[MROWS * Dc];

// Tile row stride: 64 bf16 payload padded to 72 bf16 (144 B). 144 % 128 = 16,
// so 8 consecutive ldmatrix row addresses hit 8 distinct 16B bank groups.
#define TSB 144

// ---------------------------------------------------------------------------
// helpers
// ---------------------------------------------------------------------------
__device__ __forceinline__ uint32_t smem_u32(const void* p) {
    uint32_t a;
    asm("{ .reg .u64 t; cvta.to.shared.u64 t, %1; cvt.u32.u64 %0, t; }" : "=r"(a) : "l"(p));
    return a;
}
__device__ __forceinline__ void ldsm4(uint32_t* r, uint32_t addr) {
    asm volatile("ldmatrix.sync.aligned.m8n8.x4.shared.b16 {%0,%1,%2,%3}, [%4];"
                 : "=r"(r[0]), "=r"(r[1]), "=r"(r[2]), "=r"(r[3]) : "r"(addr));
}
__device__ __forceinline__ void ldsm2(uint32_t* r, uint32_t addr) {
    asm volatile("ldmatrix.sync.aligned.m8n8.x2.shared.b16 {%0,%1}, [%2];"
                 : "=r"(r[0]), "=r"(r[1]) : "r"(addr));
}
__device__ __forceinline__ void mma16816(float* d, const uint32_t* a, const uint32_t* b) {
    asm volatile("mma.sync.aligned.m16n8k16.row.col.f32.bf16.bf16.f32 "
                 "{%0,%1,%2,%3}, {%4,%5,%6,%7}, {%8,%9}, {%0,%1,%2,%3};"
                 : "+f"(d[0]), "+f"(d[1]), "+f"(d[2]), "+f"(d[3])
                 : "r"(a[0]), "r"(a[1]), "r"(a[2]), "r"(a[3]), "r"(b[0]), "r"(b[1]));
}

// fp32 -> (hi, lo) bf16 split, 8 elements, packed as 4x uint32 (bf16x2)
__device__ __forceinline__ void cvt8(const float* f, uint32_t* hi2, uint32_t* lo2) {
    #pragma unroll
    for (int i = 0; i < 4; i++) {
        float x0 = f[2 * i], x1 = f[2 * i + 1];
        __nv_bfloat16 h0 = __float2bfloat16_rn(x0);
        __nv_bfloat16 h1 = __float2bfloat16_rn(x1);
        float r0 = x0 - __bfloat162float(h0);
        float r1 = x1 - __bfloat162float(h1);
        __nv_bfloat16 l0 = __float2bfloat16_rn(r0);
        __nv_bfloat16 l1 = __float2bfloat16_rn(r1);
        uint32_t ha = *(const uint16_t*)&h0, hb = *(const uint16_t*)&h1;
        uint32_t la = *(const uint16_t*)&l0, lb = *(const uint16_t*)&l1;
        hi2[i] = ha | (hb << 16);
        lo2[i] = la | (lb << 16);
    }
}

// Fill a [rows x 64] bf16 hi/lo tile pair (row stride TSB) from fp32 global.
__device__ __forceinline__ void fill_hilo(char* hi, char* lo, const float* g,
                                          int ldg, int rows, int tid) {
    const int units = rows * 8;
    for (int u = tid; u < units; u += 256) {
        int r = u >> 3, s = u & 7;
        const float* p = g + (size_t)r * ldg + s * 8;
        float f[8];
        *(float4*)&f[0] = *(const float4*)&p[0];
        *(float4*)&f[4] = *(const float4*)&p[4];
        uint32_t h[4], l[4];
        cvt8(f, h, l);
        const int off = r * TSB + s * 16;
        *(uint4*)(hi + off) = make_uint4(h[0], h[1], h[2], h[3]);
        *(uint4*)(lo + off) = make_uint4(l[0], l[1], l[2], l[3]);
    }
}

// One 64-deep K chunk of hi/lo MMAs. acc[MT][NT][4].
template <int MT, int NT>
__device__ __forceinline__ void mma_chunk(uint32_t aHi, uint32_t aLo,
                                          uint32_t bHi, uint32_t bLo,
                                          int warp_m, int warp_n, int lane,
                                          float acc[MT][NT][4]) {
    const uint32_t aRow = (uint32_t)(warp_m + (lane & 15)) * TSB;
    const uint32_t aSel = (lane >> 4) * 16;             // bytes
    const int l = lane & 15;
    const uint32_t bRow = (uint32_t)(warp_n + (l & 7)) * TSB;
    const uint32_t bSel = (l >> 3) * 16;                // bytes
    #pragma unroll
    for (int k16 = 0; k16 < 4; k16++) {
        uint32_t ah[MT][4], al[MT][4], bh[NT][2], bl[NT][2];
        const uint32_t ak = k16 * 32 + aSel;
        const uint32_t bk = k16 * 32 + bSel;
        #pragma unroll
        for (int mt = 0; mt < MT; mt++) {
            const uint32_t off = aRow + (uint32_t)(mt * 16) * TSB + ak;
            ldsm4(ah[mt], aHi + off);
            ldsm4(al[mt], aLo + off);
        }
        #pragma unroll
        for (int nt = 0; nt < NT; nt++) {
            const uint32_t off = bRow + (uint32_t)(nt * 8) * TSB + bk;
            ldsm2(bh[nt], bHi + off);
            ldsm2(bl[nt], bLo + off);
        }
        #pragma unroll
        for (int mt = 0; mt < MT; mt++)
            #pragma unroll
            for (int nt = 0; nt < NT; nt++) {
                mma16816(acc[mt][nt], ah[mt], bh[nt]);
                mma16816(acc[mt][nt], ah[mt], bl[nt]);
                mma16816(acc[mt][nt], al[mt], bh[nt]);
            }
    }
}

// ---------------------------------------------------------------------------
// Projection GEMM: C[4096,1024] = X @ W^T + bias. 128x128 tile, K=1024.
// grid (8, 32), 256 threads, 2 CTAs/SM. smem = 4 x 18432 = 73728 B.
// ---------------------------------------------------------------------------
__global__ void __launch_bounds__(256, 2)
proj_mma(const float* __restrict__ X, const float* __restrict__ W,
         const float* __restrict__ bias, float* __restrict__ C) {
    extern __shared__ char sm[];
    char* Ahi = sm;            char* Alo = sm + 18432;
    char* Bhi = sm + 36864;    char* Blo = sm + 55296;
    const uint32_t smb = smem_u32(sm);
    const uint32_t aHi = smb, aLo = smb + 18432, bHi = smb + 36864, bLo = smb + 55296;
    const int tid = threadIdx.x, wid = tid >> 5, lane = tid & 31;
    const int row0 = blockIdx.y * 128, col0 = blockIdx.x * 128;
    const int warp_m = (wid >> 2) * 64, warp_n = (wid & 3) * 32;

    float acc[4][4][4] = {};

    for (int c = 0; c < 16; c++) {
        const int kt = c * 64;
        fill_hilo(Ahi, Alo, X + (size_t)row0 * Dc + kt, Dc, 128, tid);
        fill_hilo(Bhi, Blo, W + (size_t)col0 * Dc + kt, Dc, 128, tid);
        __syncthreads();
        mma_chunk<4, 4>(aHi, aLo, bHi, bLo, warp_m, warp_n, lane, acc);
        __syncthreads();
    }

    #pragma unroll
    for (int mt = 0; mt < 4; mt++) {
        const int r = row0 + warp_m + mt * 16 + (lane >> 2);
        #pragma unroll
        for (int nt = 0; nt < 4; nt++) {
            const int col = col0 + warp_n + nt * 8 + (lane & 3) * 2;
            const float2 bb = *(const float2*)&bias[col];
            float2 o0 = make_float2(acc[mt][nt][0] + bb.x, acc[mt][nt][1] + bb.y);
            float2 o1 = make_float2(acc[mt][nt][2] + bb.x, acc[mt][nt][3] + bb.y);
            *(float2*)&C[(size_t)r * Dc + col]       = o0;
            *(float2*)&C[(size_t)(r + 8) * Dc + col] = o1;
        }
    }
}

// ---------------------------------------------------------------------------
// QK: A[bh,i,j] = 0.125 * Qh @ Kh^T. 128x128 tile, K=64 (1 chunk).
// grid (16, 16, 32), 256 threads, 2 CTAs/SM.
// ---------------------------------------------------------------------------
__global__ void __launch_bounds__(256, 2)
qk_mma(const float* __restrict__ Q, const float* __restrict__ K, float* __restrict__ A) {
    extern __shared__ char sm[];
    char* Ahi = sm;            char* Alo = sm + 18432;
    char* Bhi = sm + 36864;    char* Blo = sm + 55296;
    const uint32_t smb = smem_u32(sm);
    const uint32_t aHi = smb, aLo = smb + 18432, bHi = smb + 36864, bLo = smb + 55296;
    const int tid = threadIdx.x, wid = tid >> 5, lane = tid & 31;
    const int bh = blockIdx.z, b = bh >> 4, h = bh & 15;
    const int i0 = blockIdx.y * 128, j0 = blockIdx.x * 128;
    const int warp_m = (wid >> 2) * 64, warp_n = (wid & 3) * 32;

    const float* Qb = Q + (size_t)(b * Nc + i0) * Dc + h * HDc;
    const float* Kb = K + (size_t)(b * Nc + j0) * Dc + h * HDc;

    float acc[4][4][4] = {};

    fill_hilo(Ahi, Alo, Qb, Dc, 128, tid);
    fill_hilo(Bhi, Blo, Kb, Dc, 128, tid);
    __syncthreads();
    mma_chunk<4, 4>(aHi, aLo, bHi, bLo, warp_m, warp_n, lane, acc);

    float* Ab = A + (size_t)bh * Nc * Nc;
    #pragma unroll
    for (int mt = 0; mt < 4; mt++) {
        const int r = i0 + warp_m + mt * 16 + (lane >> 2);
        #pragma unroll
        for (int nt = 0; nt < 4; nt++) {
            const int col = j0 + warp_n + nt * 8 + (lane & 3) * 2;
            float2 o0 = make_float2(acc[mt][nt][0] * 0.125f, acc[mt][nt][1] * 0.125f);
            float2 o1 = make_float2(acc[mt][nt][2] * 0.125f, acc[mt][nt][3] * 0.125f);
            *(float2*)&Ab[(size_t)r * Nc + col]       = o0;
            *(float2*)&Ab[(size_t)(r + 8) * Nc + col] = o1;
        }
    }
}

// ---------------------------------------------------------------------------
// Row softmax in place, register-resident. 256 threads/row.
// ---------------------------------------------------------------------------
__global__ void softmax_kernel(float* __restrict__ A) {
    __shared__ float red[256];
    float4* p = (float4*)(A + (size_t)blockIdx.x * Nc);
    const int t = threadIdx.x;

    float4 v0 = p[t];
    float4 v1 = p[t + 256];

    float m = fmaxf(fmaxf(fmaxf(v0.x, v0.y), fmaxf(v0.z, v0.w)),
                    fmaxf(fmaxf(v1.x, v1.y), fmaxf(v1.z, v1.w)));
    red[t] = m;
    __syncthreads();
    #pragma unroll
    for (int s = 128; s > 0; s >>= 1) {
        if (t < s) red[t] = fmaxf(red[t], red[t + s]);
        __syncthreads();
    }
    const float mx = red[0];
    __syncthreads();

    v0.x = __expf(v0.x - mx); v0.y = __expf(v0.y - mx);
    v0.z = __expf(v0.z - mx); v0.w = __expf(v0.w - mx);
    v1.x = __expf(v1.x - mx); v1.y = __expf(v1.y - mx);
    v1.z = __expf(v1.z - mx); v1.w = __expf(v1.w - mx);

    float sum = (v0.x + v0.y + v0.z + v0.w) + (v1.x + v1.y + v1.z + v1.w);
    red[t] = sum;
    __syncthreads();
    #pragma unroll
    for (int s = 128; s > 0; s >>= 1) {
        if (t < s) red[t] += red[t + s];
        __syncthreads();
    }
    const float inv = 1.f / red[0];

    v0.x *= inv; v0.y *= inv; v0.z *= inv; v0.w *= inv;
    v1.x *= inv; v1.y *= inv; v1.z *= inv; v1.w *= inv;
    p[t] = v0;
    p[t + 256] = v1;
}

// ---------------------------------------------------------------------------
// AV: Vt[b,i,h*64+d] = A[bh] @ V_h. 128(m) x 64(n) tile, K=2048 (32 chunks).
// V transposed during smem conversion so the MMA is NT.
// grid (16, 32), 256 threads, 2 CTAs/SM. smem = 2x18432 + 2x9216 = 55296 B.
// ---------------------------------------------------------------------------
__global__ void __launch_bounds__(256, 2)
av_mma(const float* __restrict__ A, const float* __restrict__ V, float* __restrict__ Vt) {
    extern __shared__ char sm[];
    char* Ahi = sm;            char* Alo = sm + 18432;
    char* Bhi = sm + 36864;    char* Blo = sm + 46080;
    const uint32_t smb = smem_u32(sm);
    const uint32_t aHi = smb, aLo = smb + 18432, bHi = smb + 36864, bLo = smb + 46080;
    const int tid = threadIdx.x, wid = tid >> 5, lane = tid & 31;
    const int bh = blockIdx.y, b = bh >> 4, h = bh & 15;
    const int i0 = blockIdx.x * 128;
    const int warp_m = (wid >> 1) * 32, warp_n = (wid & 1) * 32;  // 4(m) x 2(n)

    const float* Ab = A + (size_t)bh * Nc * Nc + (size_t)i0 * Nc;
    const float* Vb = V + (size_t)b * Nc * Dc + h * HDc;

    float acc[2][4][4] = {};

    for (int c = 0; c < 32; c++) {
        const int j0 = c * 64;
        // A tile: 128 rows x 64 k
        fill_hilo(Ahi, Alo, Ab + j0, Nc, 128, tid);
        // V tile transposed: B[n=d][k=j] = V[j0+j][d]; 64 x 64
        for (int u = tid; u < 512; u += 256) {
            const int j = u & 63, s = u >> 6;
            const float* g = Vb + (size_t)(j0 + j) * Dc + s * 8;
            float f[8];
            *(float4*)&f[0] = *(const float4*)&g[0];
            *(float4*)&f[4] = *(const float4*)&g[4];
            #pragma unroll
            for (int e = 0; e < 8; e++) {
                const float x = f[e];
                __nv_bfloat16 hv = __float2bfloat16_rn(x);
                __nv_bfloat16 lv = __float2bfloat16_rn(x - __bfloat162float(hv));
                const int d = s * 8 + e;
                *(uint16_t*)(Bhi + d * TSB + j * 2) = *(const uint16_t*)&hv;
                *(uint16_t*)(Blo + d * TSB + j * 2) = *(const uint16_t*)&lv;
            }
        }
        __syncthreads();
        mma_chunk<2, 4>(aHi, aLo, bHi, bLo, warp_m, warp_n, lane, acc);
        __syncthreads();
    }

    #pragma unroll
    for (int mt = 0; mt < 2; mt++) {
        const int r = i0 + warp_m + mt * 16 + (lane >> 2);
        #pragma unroll
        for (int nt = 0; nt < 4; nt++) {
            const int d = warp_n + nt * 8 + (lane & 3) * 2;
            float* dst0 = &Vt[(size_t)(b * Nc + r) * Dc + h * HDc + d];
            float* dst1 = &Vt[(size_t)(b * Nc + r + 8) * Dc + h * HDc + d];
            *(float2*)dst0 = make_float2(acc[mt][nt][0], acc[mt][nt][1]);
            *(float2*)dst1 = make_float2(acc[mt][nt][2], acc[mt][nt][3]);
        }
    }
}

// ---------------------------------------------------------------------------
extern "C" void kernel_launch(void* const* d_in, const int* in_sizes, int n_in,
                              void* d_out, int out_size) {
    const float* query = (const float*)d_in[0];
    const float* key   = (const float*)d_in[1];
    const float* value = (const float*)d_in[2];
    const float* Wq = (const float*)d_in[3];
    const float* bq = (const float*)d_in[4];
    const float* Wk = (const float*)d_in[5];
    const float* bk = (const float*)d_in[6];
    const float* Wv = (const float*)d_in[7];
    const float* bv = (const float*)d_in[8];
    const float* Wo = (const float*)d_in[9];
    const float* bo = (const float*)d_in[10];

    float* out = (float*)d_out;              // [B, N, D]
    float* A   = (float*)d_out + OUT_ELEMS;  // [B, H, N, N]

    float* Q;  cudaGetSymbolAddress((void**)&Q,  g_Q);
    float* K;  cudaGetSymbolAddress((void**)&K,  g_K);
    float* V;  cudaGetSymbolAddress((void**)&V,  g_V);
    float* Vt; cudaGetSymbolAddress((void**)&Vt, g_Vt);

    const int SMEM_BIG = 4 * 18432;                 // 73728
    const int SMEM_AV  = 2 * 18432 + 2 * 9216;      // 55296
    cudaFuncSetAttribute(proj_mma, cudaFuncAttributeMaxDynamicSharedMemorySize, SMEM_BIG);
    cudaFuncSetAttribute(qk_mma,   cudaFuncAttributeMaxDynamicSharedMemorySize, SMEM_BIG);
    cudaFuncSetAttribute(av_mma,   cudaFuncAttributeMaxDynamicSharedMemorySize, SMEM_AV);

    dim3 gProj(Dc / 128, MROWS / 128);              // (8, 32)
    proj_mma<<<gProj, 256, SMEM_BIG>>>(query, Wq, bq, Q);
    proj_mma<<<gProj, 256, SMEM_BIG>>>(key,   Wk, bk, K);
    proj_mma<<<gProj, 256, SMEM_BIG>>>(value, Wv, bv, V);

    dim3 gQK(Nc / 128, Nc / 128, BH);               // (16, 16, 32)
    qk_mma<<<gQK, 256, SMEM_BIG>>>(Q, K, A);

    softmax_kernel<<<BH * Nc, 256>>>(A);

    dim3 gAV(Nc / 128, BH);                         // (16, 32)
    av_mma<<<gAV, 256, SMEM_AV>>>(A, V, Vt);

    proj_mma<<<gProj, 256, SMEM_BIG>>>(Vt, Wo, bo, out);
}